// round 17
// baseline (speedup 1.0000x reference)
#include <cuda_runtime.h>
#include <cuda_fp16.h>
#include <cstdint>

#define OH 62
#define OW 62
#define RS 72   // slab row stride in half2 units (288 B)

typedef uint32_t u32;

__device__ __forceinline__ u32 h2pack(float a, float b) {
    const __half2 h = __floats2half2_rn(a, b);
    return *(const u32*)&h;
}
__device__ __forceinline__ void hmma16(float* c, const u32* a, u32 b0, u32 b1) {
    asm volatile(
        "mma.sync.aligned.m16n8k16.row.col.f32.f16.f16.f32 "
        "{%0,%1,%2,%3}, {%4,%5,%6,%7}, {%8,%9}, {%0,%1,%2,%3};"
        : "+f"(c[0]), "+f"(c[1]), "+f"(c[2]), "+f"(c[3])
        : "r"(a[0]), "r"(a[1]), "r"(a[2]), "r"(a[3]), "r"(b0), "r"(b1));
}

// Fused Conv3d(3->16,k3,valid)+bias+minD+softmaxC via fp16 HMMA m16n8k16.
// vs R16: (1) dl fully unrolled with slab indices chunk-invariant -> depth
// offset folds into the LDS immediate (zero pointer ALU in mainloop);
// (2) MMA-even/odd cover even/odd pixels -> their B fragments are adjacent
// slab entries, fetched by ONE LDS.64 for both MMAs (28 LDS.32 -> 14 LDS.64).
__global__ __launch_bounds__(128, 4)
void conv_hmma(const float* __restrict__ x,
               const float* __restrict__ wgt,
               const float* __restrict__ bias,
               float* __restrict__ out)
{
    // slab rows: [ci(3)][dslice(10)][kh(3)] x RS half2 entries
    __shared__ u32   s_x[90 * RS];
    __shared__ float s_min[64][16];

    const int tid  = threadIdx.x;
    const int warp = tid >> 5;
    const int lane = tid & 31;
    const int g    = lane >> 2;   // groupID
    const int t    = lane & 3;    // threadID_in_group
    const int w0   = warp << 4;   // warp's 16-pixel w tile
    const int h    = blockIdx.x;  // 0..61
    const int n    = blockIdx.y;  // 0..15

    // ---- A fragments (weights) -> registers, once ----
    // K = 112: k = q*4 + s, q=(ci,kd,kh) 0..26, s=kw (s=3 -> zero pad)
    u32 wa[7][4];
#pragma unroll
    for (int j = 0; j < 7; j++) {
        const int k0 = 16 * j + 2 * t;
        float wv[2][4];
#pragma unroll
        for (int u = 0; u < 4; u++) {
            const int k = k0 + ((u >> 1) << 3) + (u & 1);   // k0,k0+1,k0+8,k0+9
            const int q = k >> 2, s = k & 3;
            float f0 = 0.f, f1 = 0.f;
            if (s != 3 && q <= 26) {
                const int ci = q / 9, kd = (q % 9) / 3, kh = q % 3;
                f0 = wgt[g * 81 + ci * 27 + kd * 9 + kh * 3 + s];
                f1 = wgt[(g + 8) * 81 + ci * 27 + kd * 9 + kh * 3 + s];
            }
            wv[0][u] = f0; wv[1][u] = f1;
        }
        wa[j][0] = h2pack(wv[0][0], wv[0][1]);
        wa[j][1] = h2pack(wv[1][0], wv[1][1]);
        wa[j][2] = h2pack(wv[0][2], wv[0][3]);
        wa[j][3] = h2pack(wv[1][2], wv[1][3]);
    }

    // ---- per-lane slab indices (u32 units), chunk-invariant ----
    // b0: k=16j+2t -> q0=4j+(t>>1), s0=(t&1)*2 ; b1: q1=q0+2, same s0.
    // entry (row(q), w0+2g+s0) = {x[.], x[.+1]}: .x feeds even-pixel MMA,
    // .y (entry+1 via uint2) feeds odd-pixel MMA.
    int idx0[7], idx1[7];
    {
        const int s0 = (t & 1) * 2;
        const int col = w0 + 2 * g + s0;
#pragma unroll
        for (int j = 0; j < 7; j++) {
            int q0 = 4 * j + (t >> 1); if (q0 > 26) q0 = 26;  // pad: weights=0
            int q1 = q0 + 2;           if (q1 > 26) q1 = 26;
            const int r0 = (q0 / 9) * 30 + ((q0 % 9) / 3) * 3 + (q0 % 3);
            const int r1 = (q1 / 9) * 30 + ((q1 % 9) / 3) * 3 + (q1 % 3);
            idx0[j] = r0 * RS + col;
            idx1[j] = r1 * RS + col;
        }
    }

    float mnE[4], mnO[4];   // even-pixel MMA, odd-pixel MMA mins
#pragma unroll
    for (int i = 0; i < 4; i++) { mnE[i] = 3.402823466e38f; mnO[i] = 3.402823466e38f; }

    const float* xn = x + (size_t)n * 786432 + h * 64;

    // ---- 8 chunks of 8 depths: d0 = 0,8,...,48, then 54 (overlap; min idem) ----
#pragma unroll 1
    for (int ch = 0; ch < 8; ch++) {
        const int d0 = (ch < 7) ? (ch << 3) : 54;

        __syncthreads();   // protect previous chunk's slab reads
        // stage slab: entry w = {x[w], x[w+1]} half2; cols 64..71 zeroed
        for (int i = tid; i < 90 * 18; i += 128) {
            const int r   = i / 18;
            const int pos = i - r * 18;
            const int ci = r / 30, rr = r % 30;
            const int dl = rr / 3, kh = rr % 3;
            uint4 o = make_uint4(0u, 0u, 0u, 0u);
            if (pos < 16) {
                const float* p = xn + ci * 262144 + (d0 + dl) * 4096
                                    + kh * 64 + pos * 4;
                const float4 v = *(const float4*)p;
                const float v4 = (pos < 15) ? p[4] : 0.f;
                o.x = h2pack(v.x, v.y);
                o.y = h2pack(v.y, v.z);
                o.z = h2pack(v.z, v.w);
                o.w = h2pack(v.w, v4);
            }
            *(uint4*)&s_x[r * RS + pos * 4] = o;
        }
        __syncthreads();

        // dl FULLY UNROLLED: depth offset dl*216 folds into LDS immediates.
#pragma unroll
        for (int dl = 0; dl < 8; dl++) {
            float aE[4] = {0,0,0,0}, bE[4] = {0,0,0,0};   // even pixels, j even/odd
            float aO[4] = {0,0,0,0}, bO[4] = {0,0,0,0};   // odd pixels
#pragma unroll
            for (int j = 0; j < 7; j++) {
                const uint2 B0 = *(const uint2*)&s_x[idx0[j] + dl * 216];
                const uint2 B1 = *(const uint2*)&s_x[idx1[j] + dl * 216];
                if ((j & 1) == 0) {
                    hmma16(aE, wa[j], B0.x, B1.x);
                    hmma16(aO, wa[j], B0.y, B1.y);
                } else {
                    hmma16(bE, wa[j], B0.x, B1.x);
                    hmma16(bO, wa[j], B0.y, B1.y);
                }
            }
#pragma unroll
            for (int i = 0; i < 4; i++) {
                mnE[i] = fminf(mnE[i], aE[i] + bE[i]);
                mnO[i] = fminf(mnO[i], aO[i] + bO[i]);
            }
        }
    }

    // ---- scatter mins ----
    // even MMA cols 2t,2t+1 -> pixels w0+4t, w0+4t+2 ; odd MMA -> +1, +3
    __syncthreads();
    s_min[w0 + 4 * t][g]          = mnE[0];
    s_min[w0 + 4 * t + 2][g]      = mnE[1];
    s_min[w0 + 4 * t][g + 8]      = mnE[2];
    s_min[w0 + 4 * t + 2][g + 8]  = mnE[3];
    s_min[w0 + 4 * t + 1][g]      = mnO[0];
    s_min[w0 + 4 * t + 3][g]      = mnO[1];
    s_min[w0 + 4 * t + 1][g + 8]  = mnO[2];
    s_min[w0 + 4 * t + 3][g + 8]  = mnO[3];
    __syncthreads();

    // ---- bias + softmax over 16 channels, one thread per valid pixel ----
    if (tid < OW) {
        float v[16];
        float mx = -3.402823466e38f;
#pragma unroll
        for (int c = 0; c < 16; c++) {
            v[c] = s_min[tid][c] + bias[c];
            mx = fmaxf(mx, v[c]);
        }
        float s = 0.f;
#pragma unroll
        for (int c = 0; c < 16; c++) {
            v[c] = __expf(v[c] - mx);
            s += v[c];
        }
        const float inv = 1.0f / s;
#pragma unroll
        for (int c = 0; c < 16; c++) {
            out[((size_t)(n * 16 + c) * OH + h) * OW + tid] = v[c] * inv;
        }
    }
}

extern "C" void kernel_launch(void* const* d_in, const int* in_sizes, int n_in,
                              void* d_out, int out_size)
{
    const float* x    = (const float*)d_in[0];  // [16,3,64,64,64]
    const float* wgt  = (const float*)d_in[1];  // [16,3,3,3,3]
    const float* bias = (const float*)d_in[2];  // [16]
    float* out = (float*)d_out;                 // [16,16,62,62]

    dim3 grid(OH, 16);   // (h, n)
    dim3 block(128);
    conv_hmma<<<grid, block>>>(x, wgt, bias, out);
}